// round 13
// baseline (speedup 1.0000x reference)
#include <cuda_runtime.h>
#include <cuda_fp16.h>

// SpatialTransformer: per-batch 3D trilinear warp, faithful to
// transform()+interpn(linear, ij) including the clipped-corner weight quirk.
//
// R13: quad pack (16B entry = full 2x2 (z,y) fp16 corner quad) + ILP x2:
//   - gather: one thread does an x-PAIR in BOTH batches (4 voxels, 8 gathers
//     in flight), trf read as 3 x LDG.64 per batch, out as 16B stores.
//   - pack: 4 voxels/thread (64B contiguous quad writes).

#define Bn 2
#define Dn 160
#define Hn 160
#define Wn 160

constexpr int NVOX = Bn * Dn * Hn * Wn;      // 8,192,000
constexpr int HWn  = Hn * Wn;                // 25,600
constexpr int BVOX = Dn * Hn * Wn;           // 4,096,000 (one batch)

// 16 bytes per voxel: the 2x2 (z,y) corner quad (C=2, fp16), y/z clamped.
__device__ uint4 g_quad[NVOX];

__device__ __forceinline__ unsigned int h2u(float a, float b)
{
    const __half2 h = __floats2half2_rn(a, b);
    return *(const unsigned int*)&h;
}

__global__ __launch_bounds__(256)
void pack_kernel(const float* __restrict__ vol)
{
    const int q = blockIdx.x * blockDim.x + threadIdx.x;   // 4-voxel group
    if (q >= NVOX / 4) return;

    const int idx = 4 * q;                     // first voxel (x % 4 == 0)
    const int yin = (idx / Wn) % Hn;           // Wn % 4 == 0 -> group shares y,z
    const int zin = (idx / HWn) % Dn;

    const int dy = (yin < Hn - 1) ? (Wn / 4) : 0;    // +1 row,   clamped (2x-float4 units)
    const int dz = (zin < Dn - 1) ? (HWn / 4) : 0;   // +1 plane, clamped

    // one "double-quad" group = 4 voxels = 2 float4 per row
    const float4* __restrict__ v4 = (const float4*)vol;
    const int p = 2 * q;                        // float4 index of group start
    const float4 f00a = __ldg(v4 + p);                  const float4 f00b = __ldg(v4 + p + 1);
    const float4 f01a = __ldg(v4 + p + 2 * dy);         const float4 f01b = __ldg(v4 + p + 2 * dy + 1);
    const float4 f10a = __ldg(v4 + p + 2 * dz);         const float4 f10b = __ldg(v4 + p + 2 * dz + 1);
    const float4 f11a = __ldg(v4 + p + 2 * dz + 2 * dy); const float4 f11b = __ldg(v4 + p + 2 * dz + 2 * dy + 1);

    uint4 e0, e1, e2, e3;
    e0.x = h2u(f00a.x, f00a.y);  e1.x = h2u(f00a.z, f00a.w);
    e2.x = h2u(f00b.x, f00b.y);  e3.x = h2u(f00b.z, f00b.w);
    e0.y = h2u(f01a.x, f01a.y);  e1.y = h2u(f01a.z, f01a.w);
    e2.y = h2u(f01b.x, f01b.y);  e3.y = h2u(f01b.z, f01b.w);
    e0.z = h2u(f10a.x, f10a.y);  e1.z = h2u(f10a.z, f10a.w);
    e2.z = h2u(f10b.x, f10b.y);  e3.z = h2u(f10b.z, f10b.w);
    e0.w = h2u(f11a.x, f11a.y);  e1.w = h2u(f11a.z, f11a.w);
    e2.w = h2u(f11b.x, f11b.y);  e3.w = h2u(f11b.z, f11b.w);

    g_quad[idx]     = e0;
    g_quad[idx + 1] = e1;
    g_quad[idx + 2] = e2;
    g_quad[idx + 3] = e3;
}

__global__ __launch_bounds__(256)
void st_warp_kernel(const float* __restrict__ trf,
                    float* __restrict__ out)
{
    const int u = blockIdx.x * blockDim.x + threadIdx.x;   // x-pair index
    // grid exact: 8000 * 256 == BVOX/2
    const int g0 = 2 * u;                       // even; x in [0,158], x+1 same row

    int x = g0 % Wn;
    int t = g0 / Wn;
    int y = t % Hn;
    const int z = t / Hn;

    // trf for voxels (g0, g0+1): 6 contiguous floats, 8B-aligned -> 3 LDG.64
    const float2* __restrict__ trf2 = (const float2*)trf;
    const int tbA = 3 * u;                      // float2 index: 3*g0 floats / 2
    const int tbB = 3 * (u + BVOX / 2);
    const float2 tA0 = __ldg(trf2 + tbA);       // {szA0, syA0}
    const float2 tA1 = __ldg(trf2 + tbA + 1);   // {sxA0, szA1}
    const float2 tA2 = __ldg(trf2 + tbA + 2);   // {syA1, sxA1}
    const float2 tB0 = __ldg(trf2 + tbB);
    const float2 tB1 = __ldg(trf2 + tbB + 1);
    const float2 tB2 = __ldg(trf2 + tbB + 2);

    const float zf = (float)z, yf = (float)y, xf = (float)x;

    // ---- per-voxel coordinate/weight computation ----
    #define COORDS(s_z, s_y, s_x, XO, DZ1, DZ0, DY1, DY0, DX1, DX0, R, X0, X1) \
        const float lz_##R = zf + (s_z);                                     \
        const float ly_##R = yf + (s_y);                                     \
        const float lx_##R = (xf + (float)(XO)) + (s_x);                     \
        float z0f_##R = fminf(fmaxf(floorf(lz_##R), 0.0f), (float)(Dn - 1)); \
        float y0f_##R = fminf(fmaxf(floorf(ly_##R), 0.0f), (float)(Hn - 1)); \
        float x0f_##R = fminf(fmaxf(floorf(lx_##R), 0.0f), (float)(Wn - 1)); \
        float z1f_##R = fminf(z0f_##R + 1.0f, (float)(Dn - 1));              \
        float y1f_##R = fminf(y0f_##R + 1.0f, (float)(Hn - 1));              \
        float x1f_##R = fminf(x0f_##R + 1.0f, (float)(Wn - 1));              \
        const float DZ1 = z1f_##R - lz_##R, DZ0 = 1.0f - DZ1;                \
        const float DY1 = y1f_##R - ly_##R, DY0 = 1.0f - DY1;                \
        const float DX1 = x1f_##R - lx_##R, DX0 = 1.0f - DX1;                \
        const int R = (int)z0f_##R * HWn + (int)y0f_##R * Wn;                \
        const int X0 = (int)x0f_##R, X1 = (int)x1f_##R;

    COORDS(tA0.x, tA0.y, tA1.x, 0, dz1A0, dz0A0, dy1A0, dy0A0, dx1A0, dx0A0, rA0, x0A0, x1A0)
    COORDS(tA1.y, tA2.x, tA2.y, 1, dz1A1, dz0A1, dy1A1, dy0A1, dx1A1, dx0A1, rA1, x0A1, x1A1)
    COORDS(tB0.x, tB0.y, tB1.x, 0, dz1B0, dz0B0, dy1B0, dy0B0, dx1B0, dx0B0, rB0, x0B0, x1B0)
    COORDS(tB1.y, tB2.x, tB2.y, 1, dz1B1, dz0B1, dy1B1, dy0B1, dx1B1, dx0B1, rB1, x0B1, x1B1)
    #undef COORDS

    // issue all 8 quad gathers before any consumption
    const uint4 eA00 = __ldg(&g_quad[rA0 + x0A0]);
    const uint4 eA01 = __ldg(&g_quad[rA0 + x1A0]);
    const uint4 eA10 = __ldg(&g_quad[rA1 + x0A1]);
    const uint4 eA11 = __ldg(&g_quad[rA1 + x1A1]);
    const uint4 eB00 = __ldg(&g_quad[BVOX + rB0 + x0B0]);
    const uint4 eB01 = __ldg(&g_quad[BVOX + rB0 + x1B0]);
    const uint4 eB10 = __ldg(&g_quad[BVOX + rB1 + x0B1]);
    const uint4 eB11 = __ldg(&g_quad[BVOX + rB1 + x1B1]);

    // collapse a quad entry over (z,y)
    #define QI(e, f, DZ1, DZ0, DY1, DY0)                                     \
    {                                                                        \
        const float2 c00 = __half22float2(*(const __half2*)&(e).x);          \
        const float2 c01 = __half22float2(*(const __half2*)&(e).y);          \
        const float2 c10 = __half22float2(*(const __half2*)&(e).z);          \
        const float2 c11 = __half22float2(*(const __half2*)&(e).w);          \
        (f).x = (DZ1) * ((DY1) * c00.x + (DY0) * c01.x)                      \
              + (DZ0) * ((DY1) * c10.x + (DY0) * c11.x);                     \
        (f).y = (DZ1) * ((DY1) * c00.y + (DY0) * c01.y)                      \
              + (DZ0) * ((DY1) * c10.y + (DY0) * c11.y);                     \
    }
    float2 fA00, fA01, fA10, fA11, fB00, fB01, fB10, fB11;
    QI(eA00, fA00, dz1A0, dz0A0, dy1A0, dy0A0);
    QI(eA01, fA01, dz1A0, dz0A0, dy1A0, dy0A0);
    QI(eA10, fA10, dz1A1, dz0A1, dy1A1, dy0A1);
    QI(eA11, fA11, dz1A1, dz0A1, dy1A1, dy0A1);
    QI(eB00, fB00, dz1B0, dz0B0, dy1B0, dy0B0);
    QI(eB01, fB01, dz1B0, dz0B0, dy1B0, dy0B0);
    QI(eB10, fB10, dz1B1, dz0B1, dy1B1, dy0B1);
    QI(eB11, fB11, dz1B1, dz0B1, dy1B1, dy0B1);
    #undef QI

    // x-collapse and 16B stores (g0 even -> float4-aligned)
    float4 oA, oB;
    oA.x = dx1A0 * fA00.x + dx0A0 * fA01.x;
    oA.y = dx1A0 * fA00.y + dx0A0 * fA01.y;
    oA.z = dx1A1 * fA10.x + dx0A1 * fA11.x;
    oA.w = dx1A1 * fA10.y + dx0A1 * fA11.y;
    oB.x = dx1B0 * fB00.x + dx0B0 * fB01.x;
    oB.y = dx1B0 * fB00.y + dx0B0 * fB01.y;
    oB.z = dx1B1 * fB10.x + dx0B1 * fB11.x;
    oB.w = dx1B1 * fB10.y + dx0B1 * fB11.y;

    ((float4*)out)[u]            = oA;
    ((float4*)out)[u + BVOX / 2] = oB;
}

extern "C" void kernel_launch(void* const* d_in, const int* in_sizes, int n_in,
                              void* d_out, int out_size)
{
    const float* vol = (const float*)d_in[0];
    const float* trf = (const float*)d_in[1];
    float* out = (float*)d_out;

    const int threads = 256;
    pack_kernel<<<(NVOX / 4 + threads - 1) / threads, threads>>>(vol);
    st_warp_kernel<<<(BVOX / 2) / threads, threads>>>(trf, out);
}

// round 15
// speedup vs baseline: 1.0287x; 1.0287x over previous
#include <cuda_runtime.h>
#include <cuda_fp16.h>

// SpatialTransformer: per-batch 3D trilinear warp, faithful to
// transform()+interpn(linear, ij) including the clipped-corner weight quirk:
//   loc0c = clip(floor(loc), 0, max); loc1c = clip(loc0c+1, 0, max)
//   d1 = loc1c - loc (weight for FLOOR corner), d0 = 1 - d1 (CEIL corner)
//
// R14:
//   - pack: register-tiled 2x2x2 — one thread builds 8 quad entries from
//     9 float4 reads (3 planes x 3 rows x 1 float4). L2 read amplification
//     4x -> 2.25x. No smem, no barriers.
//   - gather: x-pair in ONE batch per thread (4 scattered quad gathers, same
//     as R12) with vectorized trf (3 x LDG.64) and one STG.128 out.

#define Bn 2
#define Dn 160
#define Hn 160
#define Wn 160

constexpr int NVOX = Bn * Dn * Hn * Wn;      // 8,192,000
constexpr int HWn  = Hn * Wn;                // 25,600
constexpr int BVOX = Dn * Hn * Wn;           // 4,096,000 (one batch)

// 16 bytes per voxel: the 2x2 (z,y) corner quad (C=2, fp16), y/z clamped:
//   e[b,z,y,x] = { h2 v[z,y,x], h2 v[z,y+1c,x], h2 v[z+1c,y,x], h2 v[z+1c,y+1c,x] }
__device__ uint4 g_quad[NVOX];

__device__ __forceinline__ unsigned int h2u(float a, float b)
{
    const __half2 h = __floats2half2_rn(a, b);
    return *(const unsigned int*)&h;
}

// one thread: 2x2x2 voxel block (2 planes, 2 rows, one x-pair)
__global__ __launch_bounds__(256)
void pack_kernel(const float* __restrict__ vol)
{
    const int q = blockIdx.x * blockDim.x + threadIdx.x;
    // groups: Bn * (Dn/2) * (Hn/2) * (Wn/2) = 1,024,000; grid exact (4000*256)

    const int gx = q % (Wn / 2);
    int t = q / (Wn / 2);
    const int gy = t % (Hn / 2);
    t /= (Hn / 2);
    const int gz = t % (Dn / 2);
    const int b  = t / (Dn / 2);

    const int z0 = 2 * gz, y0 = 2 * gy;
    const int z2 = (z0 + 2 < Dn) ? (z0 + 2) : (Dn - 1);   // clamped third plane
    const int y2 = (y0 + 2 < Hn) ? (y0 + 2) : (Hn - 1);   // clamped third row

    const float4* __restrict__ v4 = (const float4*)vol;   // 1 float4 = 2 voxels
    const int bbase = b * BVOX;

    // float4 index of (z, y) row at this x-pair: (bbase + z*HWn + y*Wn)/2 + gx
    #define RQ(zz, yy) ((bbase + (zz) * HWn + (yy) * Wn) / 2 + gx)

    // 9 reads: planes {z0, z0+1, z2} x rows {y0, y0+1, y2}
    const float4 f00 = __ldg(v4 + RQ(z0,     y0));
    const float4 f01 = __ldg(v4 + RQ(z0,     y0 + 1));
    const float4 f02 = __ldg(v4 + RQ(z0,     y2));
    const float4 f10 = __ldg(v4 + RQ(z0 + 1, y0));
    const float4 f11 = __ldg(v4 + RQ(z0 + 1, y0 + 1));
    const float4 f12 = __ldg(v4 + RQ(z0 + 1, y2));
    const float4 f20 = __ldg(v4 + RQ(z2,     y0));
    const float4 f21 = __ldg(v4 + RQ(z2,     y0 + 1));
    const float4 f22 = __ldg(v4 + RQ(z2,     y2));
    #undef RQ

    // convert once: 9 rows x 2 x-slots of half2
    unsigned int h[3][3][2];
    #define CV(zi, yi, f) h[zi][yi][0] = h2u((f).x, (f).y); h[zi][yi][1] = h2u((f).z, (f).w);
    CV(0,0,f00) CV(0,1,f01) CV(0,2,f02)
    CV(1,0,f10) CV(1,1,f11) CV(1,2,f12)
    CV(2,0,f20) CV(2,1,f21) CV(2,2,f22)
    #undef CV

    // 8 quad entries: (dz, dy) in {0,1}^2, x-slot s in {0,1}
    #pragma unroll
    for (int dz = 0; dz < 2; dz++) {
        #pragma unroll
        for (int dy = 0; dy < 2; dy++) {
            const int ez = z0 + dz, ey = y0 + dy;
            const int eidx = bbase + ez * HWn + ey * Wn + 2 * gx;
            #pragma unroll
            for (int s = 0; s < 2; s++) {
                uint4 e;
                e.x = h[dz][dy][s];          // (z,   y  )
                e.y = h[dz][dy + 1][s];      // (z,   y+1)  (row 2 is clamped copy)
                e.z = h[dz + 1][dy][s];      // (z+1, y  )
                e.w = h[dz + 1][dy + 1][s];  // (z+1, y+1)
                g_quad[eidx + s] = e;
            }
        }
    }
}

__global__ __launch_bounds__(256)
void st_warp_kernel(const float* __restrict__ trf,
                    float* __restrict__ out)
{
    const int u = blockIdx.x * blockDim.x + threadIdx.x;   // x-pair index over ALL voxels
    // grid exact: 16000 * 256 == NVOX/2
    const int g0 = 2 * u;                   // even; x and x+1 share the row

    int x = g0 % Wn;
    int t = g0 / Wn;
    int y = t % Hn;
    t /= Hn;
    const int z = t % Dn;
    const int b = t / Dn;

    // trf for voxels (g0, g0+1): 6 contiguous floats -> 3 LDG.64
    const float2* __restrict__ trf2 = (const float2*)trf;
    const float2 t0 = __ldg(trf2 + 3 * u);       // {sz0, sy0}
    const float2 t1 = __ldg(trf2 + 3 * u + 1);   // {sx0, sz1}
    const float2 t2 = __ldg(trf2 + 3 * u + 2);   // {sy1, sx1}

    const float zf = (float)z, yf = (float)y, xf = (float)x;
    const int bq = b * BVOX;

    #define COORDS(s_z, s_y, s_x, XO, DZ1, DZ0, DY1, DY0, DX1, DX0, R, X0, X1) \
        const float lz_##R = zf + (s_z);                                     \
        const float ly_##R = yf + (s_y);                                     \
        const float lx_##R = (xf + (float)(XO)) + (s_x);                     \
        float z0f_##R = fminf(fmaxf(floorf(lz_##R), 0.0f), (float)(Dn - 1)); \
        float y0f_##R = fminf(fmaxf(floorf(ly_##R), 0.0f), (float)(Hn - 1)); \
        float x0f_##R = fminf(fmaxf(floorf(lx_##R), 0.0f), (float)(Wn - 1)); \
        float z1f_##R = fminf(z0f_##R + 1.0f, (float)(Dn - 1));              \
        float y1f_##R = fminf(y0f_##R + 1.0f, (float)(Hn - 1));              \
        float x1f_##R = fminf(x0f_##R + 1.0f, (float)(Wn - 1));              \
        const float DZ1 = z1f_##R - lz_##R, DZ0 = 1.0f - DZ1;                \
        const float DY1 = y1f_##R - ly_##R, DY0 = 1.0f - DY1;                \
        const float DX1 = x1f_##R - lx_##R, DX0 = 1.0f - DX1;                \
        const int R = bq + (int)z0f_##R * HWn + (int)y0f_##R * Wn;           \
        const int X0 = (int)x0f_##R, X1 = (int)x1f_##R;

    COORDS(t0.x, t0.y, t1.x, 0, dz1_r0, dz0_r0, dy1_r0, dy0_r0, dx1_r0, dx0_r0, r0, x0_r0, x1_r0)
    COORDS(t1.y, t2.x, t2.y, 1, dz1_r1, dz0_r1, dy1_r1, dy0_r1, dx1_r1, dx0_r1, r1, x0_r1, x1_r1)
    #undef COORDS

    // 4 scattered 16B quad gathers, issued before any consumption
    const uint4 e00 = __ldg(&g_quad[r0 + x0_r0]);
    const uint4 e01 = __ldg(&g_quad[r0 + x1_r0]);
    const uint4 e10 = __ldg(&g_quad[r1 + x0_r1]);
    const uint4 e11 = __ldg(&g_quad[r1 + x1_r1]);

    // collapse a quad entry over (z,y)
    #define QI(e, f, DZ1, DZ0, DY1, DY0)                                     \
    {                                                                        \
        const float2 c00 = __half22float2(*(const __half2*)&(e).x);          \
        const float2 c01 = __half22float2(*(const __half2*)&(e).y);          \
        const float2 c10 = __half22float2(*(const __half2*)&(e).z);          \
        const float2 c11 = __half22float2(*(const __half2*)&(e).w);          \
        (f).x = (DZ1) * ((DY1) * c00.x + (DY0) * c01.x)                      \
              + (DZ0) * ((DY1) * c10.x + (DY0) * c11.x);                     \
        (f).y = (DZ1) * ((DY1) * c00.y + (DY0) * c01.y)                      \
              + (DZ0) * ((DY1) * c10.y + (DY0) * c11.y);                     \
    }
    float2 f00, f01, f10, f11;
    QI(e00, f00, dz1_r0, dz0_r0, dy1_r0, dy0_r0);
    QI(e01, f01, dz1_r0, dz0_r0, dy1_r0, dy0_r0);
    QI(e10, f10, dz1_r1, dz0_r1, dy1_r1, dy0_r1);
    QI(e11, f11, dz1_r1, dz0_r1, dy1_r1, dy0_r1);
    #undef QI

    // x-collapse; one 16B store (g0 even -> aligned)
    float4 o;
    o.x = dx1_r0 * f00.x + dx0_r0 * f01.x;
    o.y = dx1_r0 * f00.y + dx0_r0 * f01.y;
    o.z = dx1_r1 * f10.x + dx0_r1 * f11.x;
    o.w = dx1_r1 * f10.y + dx0_r1 * f11.y;
    ((float4*)out)[u] = o;
}

extern "C" void kernel_launch(void* const* d_in, const int* in_sizes, int n_in,
                              void* d_out, int out_size)
{
    const float* vol = (const float*)d_in[0];
    const float* trf = (const float*)d_in[1];
    float* out = (float*)d_out;

    const int threads = 256;
    constexpr int NGROUPS = Bn * (Dn / 2) * (Hn / 2) * (Wn / 2);  // 1,024,000
    pack_kernel<<<NGROUPS / threads, threads>>>(vol);
    st_warp_kernel<<<(NVOX / 2) / threads, threads>>>(trf, out);
}